// round 13
// baseline (speedup 1.0000x reference)
#include <cuda_runtime.h>
#include <cuda_bf16.h>
#include <math.h>

// Static shapes: B=2048, D=256, K = D/2-1 = 127. Output R[2048,256,256] fp32.
// Nonzeros (even rows r only):
//   col r-2 -> sin(p*theta_{(r-2)/2})    (r >= 2)
//   col r   -> cos(p*theta_{min(r/2,126)})
//   col r+2 -> -sin(p*theta_{r/2})       (r/2 <= 126)
// theta_i = 10000^(-2*(i-1)/256)
//
// Grid: 8192 blocks = 2048 matrices x 4 chunks. Chunk q owns row-groups
// [16q,16q+16). Thread tid = h*64+j owns quad (k0+k)*256+tid, k=0..15.
//
// R13 vs R12: single-pass stores. Each patch thread computes its <=2 patch
// float4 values privately (no shared table, no __syncthreads), and the store
// loop SELECTS the value per iteration — every thread still issues all 16
// full-width warp-uniform STG.128s (R7's fragmentation avoided), but each
// quad is written exactly once (-1.6% traffic, barrier eliminated).

#define K_ITERS 127

// theta in double (then fp32) matches the reference fp32 phase to ~1 ulp.
__device__ __forceinline__ void rope_sincos(int i, int p, float* s, float* c) {
    const double e = -2.0 * ((double)i - 1.0) / 256.0;
    const float theta = (float)exp(e * 9.210340371976184);  // ln(10000)
    const float m = (float)p * theta;
    *s = sinf(m);
    *c = cosf(m);
}
__device__ __forceinline__ float rope_sin(int i, int p) {
    float s, c; rope_sincos(i, p, &s, &c); return s;
}

__global__ __launch_bounds__(256) void rope_kernel(float4* __restrict__ out) {
    const int tid = threadIdx.x;
    const int p   = blockIdx.x >> 2;
    const int q   = blockIdx.x & 3;
    const int k0  = q << 4;              // first row-group of this chunk
    const int k1  = k0 + 16;
    const int h   = tid >> 6;
    const int j   = tid & 63;

    // Precompute this thread's patch values (h=1,3 lanes skip all math).
    const float4 z = make_float4(0.f, 0.f, 0.f, 0.f);
    float4 va = z, vb = z;
    int ka = -1, kb = -1;
    if (h == 0) {
        if (j >= k0 && j < k1) {
            // row 4j, quad j: .x = cos_{2j}, .z = -sin_{2j}
            float s, c; rope_sincos(2 * j, p, &s, &c);
            va = make_float4(c, 0.f, -s, 0.f);
            ka = j - k0;
        }
        if (j <= 62 && (j + 1) >= k0 && (j + 1) < k1) {
            // row 4j+4, quad j: .z = sin_{2j+1}
            vb = make_float4(0.f, 0.f, rope_sin(2 * j + 1, p), 0.f);
            kb = j + 1 - k0;
        }
    } else if (h == 2) {
        if (j >= k0 && j < k1) {
            // row 4j+2, quad j: .x = sin_{2j}, .z = cos_{min(2j+1,126)}
            int i = 2 * j + 1; if (i > K_ITERS - 1) i = K_ITERS - 1;
            float s2j = rope_sin(2 * j, p);
            float si, ci; rope_sincos(i, p, &si, &ci);
            va = make_float4(s2j, 0.f, ci, 0.f);
            ka = j - k0;
        }
        if (j >= 1 && (j - 1) >= k0 && (j - 1) < k1) {
            // row 4j-2, quad j: .x = -sin_{2j-1}
            vb = make_float4(-rope_sin(2 * j - 1, p), 0.f, 0.f, 0.f);
            kb = j - 1 - k0;
        }
    }

    // Single-pass store stream: full-width, warp-uniform, each quad once.
    float4* zbase = out + ((size_t)p << 14) + ((size_t)k0 << 8) + tid;
#pragma unroll
    for (int k = 0; k < 16; k++) {
        float4 v = z;
        if (k == ka) v = va;
        if (k == kb) v = vb;
        __stcs(&zbase[k << 8], v);       // STG.E.128.CS [R + k*4096]
    }
}

extern "C" void kernel_launch(void* const* d_in, const int* in_sizes, int n_in,
                              void* d_out, int out_size) {
    (void)d_in; (void)in_sizes; (void)n_in; (void)out_size;
    rope_kernel<<<8192, 256, 0, 0>>>((float4*)d_out);
}